// round 6
// baseline (speedup 1.0000x reference)
#include <cuda_runtime.h>
#include <cuda_bf16.h>

// Problem constants: B=8, C=256, H=W=64, OG=4, Cg=64, K=9 taps, off channels=72.
#define BATCH 8
#define CIN   256
#define HH    64
#define WW    64
#define OG    4
#define CG    64
#define OFFC  72   // 2*9*OG

// ---------------- device scratch (static, allocation-free) ----------------
__device__ float g_off[BATCH * OFFC * HH * WW];        // stage-1 output: offsets
__device__ float g_woff_r[2304 * OFFC];                // w_off transposed: [(ci*9+k)][co]
__device__ float g_wdef_r[OG * 9 * CG * CG];           // w_def reordered: [og][k][cg][o]

// ---------------- weight reorder (one-time-ish, tiny) ----------------
__global__ void reorder_weights(const float* __restrict__ w_off,
                                const float* __restrict__ w_def) {
    int i = blockIdx.x * 256 + threadIdx.x;
    // w_off [72][256][3][3] -> g_woff_r[row=ci*9+k][co]
    if (i < 2304 * OFFC) {
        int row = i / OFFC, co = i % OFFC;
        g_woff_r[i] = w_off[co * 2304 + row];
    }
    // w_def [256][64][3][3] -> g_wdef_r[((og*9+k)*64+cg)*64+o]
    if (i < OG * 9 * CG * CG) {
        int o  = i & 63;
        int t  = i >> 6;
        int cg = t & 63;
        t >>= 6;
        int k  = t % 9;
        int og = t / 9;
        g_wdef_r[i] = w_def[((og * CG + o) * CG + cg) * 9 + k];
    }
}

// ---------------- stage 1: offsets = conv3x3(x, w_off) + b_off ----------------
// Block: (b, pair of rows h0,h0+1). Output tile 80(pad of 72) couts x 128 pixels.
// Threads 256 = 16x16; thread tile = 5 couts x 8 pixels (2 rows x 4 cols).
// K loop over ci in chunks of 16; x rows staged with halo, weights transposed.
__global__ void __launch_bounds__(256, 2)
offsets_conv(const float* __restrict__ x, const float* __restrict__ b_off) {
    extern __shared__ float sm[];
    float* xs = sm;             // [16][4][68]  (rows h0-1..h0+2, cols = w+1, 0..65 used)
    float* ws = sm + 16*4*68;   // [144][80]    ((ci*9+k) local, co padded to 80)

    const int b  = blockIdx.y;
    const int h0 = blockIdx.x * 2;
    const int t  = threadIdx.x;
    const int tx = t & 15, ty = t >> 4;
    const int w4 = tx * 4, o0 = ty * 5;

    float acc[5][2][4];
    #pragma unroll
    for (int o = 0; o < 5; o++)
        #pragma unroll
        for (int r = 0; r < 2; r++)
            #pragma unroll
            for (int p = 0; p < 4; p++) acc[o][r][p] = 0.f;

    for (int cc = 0; cc < 16; cc++) {
        const int ci0 = cc * 16;
        __syncthreads();
        // stage x chunk: [16 ci][4 rows][66 cols]
        for (int j = t; j < 16 * 4 * 66; j += 256) {
            int c  = j % 66;
            int rc = j / 66;
            int r  = rc & 3;
            int ci = rc >> 2;
            int gh = h0 - 1 + r, gw = c - 1;
            float v = 0.f;
            if ((unsigned)gh < (unsigned)HH && (unsigned)gw < (unsigned)WW)
                v = x[(((b << 8) + ci0 + ci) * HH + gh) * WW + gw];
            xs[(ci * 4 + r) * 68 + c] = v;
        }
        // stage weight chunk: 144 rows x 72 couts (coalesced from reordered buf)
        for (int j = t; j < 144 * OFFC; j += 256) {
            int row = j / OFFC, co = j % OFFC;
            ws[row * 80 + co] = g_woff_r[(ci0 * 9 + row) * OFFC + co];
        }
        __syncthreads();

        #pragma unroll 1
        for (int ci = 0; ci < 16; ci++) {
            float xr[4][6];
            #pragma unroll
            for (int r = 0; r < 4; r++) {
                const float* xp = &xs[(ci * 4 + r) * 68 + w4];
                float4 v4 = *(const float4*)xp;
                xr[r][0] = v4.x; xr[r][1] = v4.y; xr[r][2] = v4.z; xr[r][3] = v4.w;
                xr[r][4] = xp[4]; xr[r][5] = xp[5];
            }
            #pragma unroll
            for (int k = 0; k < 9; k++) {
                const int ky = k / 3, kx = k % 3;
                const float* wp = &ws[(ci * 9 + k) * 80 + o0];
                #pragma unroll
                for (int o = 0; o < 5; o++) {
                    float wv = wp[o];
                    #pragma unroll
                    for (int r = 0; r < 2; r++)
                        #pragma unroll
                        for (int p = 0; p < 4; p++)
                            acc[o][r][p] = fmaf(wv, xr[r + ky][p + kx], acc[o][r][p]);
                }
            }
        }
    }

    #pragma unroll
    for (int o = 0; o < 5; o++) {
        int co = o0 + o;
        if (co < OFFC) {
            float bias = b_off[co];
            #pragma unroll
            for (int r = 0; r < 2; r++) {
                float4 v = make_float4(acc[o][r][0] + bias, acc[o][r][1] + bias,
                                       acc[o][r][2] + bias, acc[o][r][3] + bias);
                *(float4*)&g_off[((b * OFFC + co) * HH + h0 + r) * WW + w4] = v;
            }
        }
    }
}

// ---------------- stage 2: deformable conv ----------------
// Block: (b, og, row-pair h0). Output tile 64 couts x 128 pixels.
// Phase 1: precompute bilinear params per (tap, pixel) -> smem (invalid corners
//          get weight 0 / index 0, identical to reference's mask-and-clip).
// Per tap: sample s[64cg][128px] from gmem (L2-resident x), load w slab, GEMM.
// Threads 256 = 32x8; GEMM thread tile = 8 couts x 4 pixels.
__global__ void __launch_bounds__(256, 2)
deform_conv(const float* __restrict__ x, const float* __restrict__ b_def,
            float* __restrict__ out) {
    extern __shared__ float sm[];
    int*   pidx = (int*)sm;                 // [9][128][4]
    float* pwt  = sm + 9 * 128 * 4;         // [9][128][4]
    float* s    = sm + 2 * 9 * 128 * 4;     // [64][128]
    float* wts  = s + CG * 128;             // [64][64]

    const int b  = blockIdx.z;
    const int og = blockIdx.y;
    const int h0 = blockIdx.x * 2;
    const int t  = threadIdx.x;

    // ---- phase 1: bilinear params for 9 taps x 128 pixels ----
    const float* offp = g_off + (b * OFFC + og * 18) * (HH * WW);
    for (int e = t; e < 9 * 128; e += 256) {
        int k = e >> 7, p = e & 127;
        int r = p >> 6, w = p & 63;
        int h = h0 + r;
        float dy = offp[(2 * k) * (HH * WW) + h * WW + w];
        float dx = offp[(2 * k + 1) * (HH * WW) + h * WW + w];
        float py = dy + (float)(k / 3 - 1) + (float)h;
        float px = dx + (float)(k % 3 - 1) + (float)w;
        float fy = floorf(py), fx = floorf(px);
        int   y0 = (int)fy,   x0 = (int)fx;
        float ly = py - fy,   lx = px - fx;
        float wy0 = 1.f - ly, wx0 = 1.f - lx;
        float cw[4] = {wy0 * wx0, wy0 * lx, ly * wx0, ly * lx};
        int   ys[4] = {y0, y0, y0 + 1, y0 + 1};
        int   xc[4] = {x0, x0 + 1, x0, x0 + 1};
        int base = e * 4;
        #pragma unroll
        for (int j = 0; j < 4; j++) {
            bool v = (unsigned)ys[j] < (unsigned)HH && (unsigned)xc[j] < (unsigned)WW;
            pidx[base + j] = v ? ys[j] * WW + xc[j] : 0;
            pwt [base + j] = v ? cw[j] : 0.f;
        }
    }
    __syncthreads();

    const int tx = t & 31, ty = t >> 5;
    const int p4 = tx * 4, o8 = ty * 8;
    const int pr = p4 >> 6, pw = p4 & 63;

    float acc[8][4];
    #pragma unroll
    for (int o = 0; o < 8; o++)
        #pragma unroll
        for (int p = 0; p < 4; p++) acc[o][p] = 0.f;

    const float* xplane = x + (b * CIN + og * CG) * (HH * WW);
    const float* wsrc   = g_wdef_r + (og * 9) * (CG * CG);
    const int sp   = t & 127;           // sampling pixel (0..127)
    const int scg0 = (t >> 7) * 32;     // sampling channel base (0 or 32)

    #pragma unroll 1
    for (int k = 0; k < 9; k++) {
        // stage this tap's 64x64 weight slab (coalesced)
        for (int j = t; j < CG * CG; j += 256)
            wts[j] = wsrc[k * CG * CG + j];
        // sample 32 channels for my pixel
        const int4   iv = *(const int4*)  &pidx[(k * 128 + sp) * 4];
        const float4 wv = *(const float4*)&pwt [(k * 128 + sp) * 4];
        const float* xc = xplane + scg0 * (HH * WW);
        #pragma unroll 4
        for (int c = 0; c < 32; c++) {
            float v = wv.x * __ldg(xc + iv.x)
                    + wv.y * __ldg(xc + iv.y)
                    + wv.z * __ldg(xc + iv.z)
                    + wv.w * __ldg(xc + iv.w);
            s[(scg0 + c) * 128 + sp] = v;
            xc += HH * WW;
        }
        __syncthreads();
        // 64x128 += 64x64 * 64x128 (this tap)
        #pragma unroll 4
        for (int cg = 0; cg < CG; cg++) {
            float4 sv = *(const float4*)&s[cg * 128 + p4];
            float4 a0 = *(const float4*)&wts[cg * CG + o8];
            float4 a1 = *(const float4*)&wts[cg * CG + o8 + 4];
            float wvv[8] = {a0.x, a0.y, a0.z, a0.w, a1.x, a1.y, a1.z, a1.w};
            float svv[4] = {sv.x, sv.y, sv.z, sv.w};
            #pragma unroll
            for (int o = 0; o < 8; o++)
                #pragma unroll
                for (int p = 0; p < 4; p++)
                    acc[o][p] = fmaf(wvv[o], svv[p], acc[o][p]);
        }
        __syncthreads();
    }

    // epilogue: add bias, store
    #pragma unroll
    for (int o = 0; o < 8; o++) {
        float bias = b_def[og * CG + o8 + o];
        float4 v = make_float4(acc[o][0] + bias, acc[o][1] + bias,
                               acc[o][2] + bias, acc[o][3] + bias);
        *(float4*)&out[((b * CIN + og * CG + o8 + o) * HH + h0 + pr) * WW + pw] = v;
    }
}

// ---------------- launch ----------------
extern "C" void kernel_launch(void* const* d_in, const int* in_sizes, int n_in,
                              void* d_out, int out_size) {
    const float* x     = (const float*)d_in[0];
    const float* w_off = (const float*)d_in[1];
    const float* b_off = (const float*)d_in[2];
    const float* w_def = (const float*)d_in[3];
    const float* b_def = (const float*)d_in[4];
    float* out = (float*)d_out;

    const int smem1 = (16 * 4 * 68 + 144 * 80) * 4;                 // 63488 B
    const int smem2 = (2 * 9 * 128 * 4 + CG * 128 + CG * CG) * 4;   // 86016 B
    cudaFuncSetAttribute(offsets_conv, cudaFuncAttributeMaxDynamicSharedMemorySize, smem1);
    cudaFuncSetAttribute(deform_conv,  cudaFuncAttributeMaxDynamicSharedMemorySize, smem2);

    reorder_weights<<<648, 256>>>(w_off, w_def);
    offsets_conv<<<dim3(HH / 2, BATCH), 256, smem1>>>(x, b_off);
    deform_conv<<<dim3(HH / 2, OG, BATCH), 256, smem2>>>(x, b_def, out);
}

// round 9
// speedup vs baseline: 1.0668x; 1.0668x over previous
#include <cuda_runtime.h>
#include <cuda_bf16.h>
#include <cstdint>

// Problem constants: B=8, C=256, H=W=64, OG=4, Cg=64, K=9 taps, off channels=72.
#define BATCH 8
#define CIN   256
#define HH    64
#define WW    64
#define OG    4
#define CG    64
#define OFFC  72   // 2*9*OG

// s tile stride (pad 128->136 so B-fragment LDS is bank-conflict-free)
#define SPAD 136
// w tile stride (pad 64->68 so A-fragment LDS is bank-conflict-free)
#define WPAD 68

// ---------------- device scratch (static, allocation-free) ----------------
__device__ float g_off[BATCH * OFFC * HH * WW];     // stage-1 output: offsets
__device__ float g_woff_r[2304 * OFFC];             // w_off transposed: [(ci*9+k)][co]
__device__ float g_wdef_r[OG * 9 * CG * CG];        // w_def reordered [og][k][cg][co], tf32-rounded

__device__ __forceinline__ float to_tf32(float f) {
    uint32_t u;
    asm("cvt.rna.tf32.f32 %0, %1;" : "=r"(u) : "f"(f));
    return __uint_as_float(u);
}

// D(16x8) += A(16x8, row) * B(8x8, col), tf32 inputs, f32 accum
__device__ __forceinline__ void mma16n8k8(float* d, const uint32_t* a, uint32_t b0, uint32_t b1) {
    asm volatile(
        "mma.sync.aligned.m16n8k8.row.col.f32.tf32.tf32.f32 "
        "{%0,%1,%2,%3}, {%4,%5,%6,%7}, {%8,%9}, {%0,%1,%2,%3};"
        : "+f"(d[0]), "+f"(d[1]), "+f"(d[2]), "+f"(d[3])
        : "r"(a[0]), "r"(a[1]), "r"(a[2]), "r"(a[3]), "r"(b0), "r"(b1));
}

// ---------------- weight reorder (one-time-ish, tiny) ----------------
__global__ void reorder_weights(const float* __restrict__ w_off,
                                const float* __restrict__ w_def) {
    int i = blockIdx.x * 256 + threadIdx.x;
    // w_off [72][256][3][3] -> g_woff_r[row=ci*9+k][co]
    if (i < 2304 * OFFC) {
        int row = i / OFFC, co = i % OFFC;
        g_woff_r[i] = w_off[co * 2304 + row];
    }
    // w_def [256][64][3][3] -> g_wdef_r[((og*9+k)*64+cg)*64+co], rounded to tf32
    if (i < OG * 9 * CG * CG) {
        int co = i & 63;
        int t  = i >> 6;
        int cg = t & 63;
        t >>= 6;
        int k  = t % 9;
        int og = t / 9;
        g_wdef_r[i] = to_tf32(w_def[((og * CG + co) * CG + cg) * 9 + k]);
    }
}

// ---------------- stage 1: offsets = conv3x3(x, w_off) + b_off (fp32, unchanged) ----------------
__global__ void __launch_bounds__(256, 2)
offsets_conv(const float* __restrict__ x, const float* __restrict__ b_off) {
    extern __shared__ float sm[];
    float* xs = sm;             // [16][4][68]
    float* ws = sm + 16*4*68;   // [144][80]

    const int b  = blockIdx.y;
    const int h0 = blockIdx.x * 2;
    const int t  = threadIdx.x;
    const int tx = t & 15, ty = t >> 4;
    const int w4 = tx * 4, o0 = ty * 5;

    float acc[5][2][4];
    #pragma unroll
    for (int o = 0; o < 5; o++)
        #pragma unroll
        for (int r = 0; r < 2; r++)
            #pragma unroll
            for (int p = 0; p < 4; p++) acc[o][r][p] = 0.f;

    for (int cc = 0; cc < 16; cc++) {
        const int ci0 = cc * 16;
        __syncthreads();
        for (int j = t; j < 16 * 4 * 66; j += 256) {
            int c  = j % 66;
            int rc = j / 66;
            int r  = rc & 3;
            int ci = rc >> 2;
            int gh = h0 - 1 + r, gw = c - 1;
            float v = 0.f;
            if ((unsigned)gh < (unsigned)HH && (unsigned)gw < (unsigned)WW)
                v = x[(((b << 8) + ci0 + ci) * HH + gh) * WW + gw];
            xs[(ci * 4 + r) * 68 + c] = v;
        }
        for (int j = t; j < 144 * OFFC; j += 256) {
            int row = j / OFFC, co = j % OFFC;
            ws[row * 80 + co] = g_woff_r[(ci0 * 9 + row) * OFFC + co];
        }
        __syncthreads();

        #pragma unroll 1
        for (int ci = 0; ci < 16; ci++) {
            float xr[4][6];
            #pragma unroll
            for (int r = 0; r < 4; r++) {
                const float* xp = &xs[(ci * 4 + r) * 68 + w4];
                float4 v4 = *(const float4*)xp;
                xr[r][0] = v4.x; xr[r][1] = v4.y; xr[r][2] = v4.z; xr[r][3] = v4.w;
                xr[r][4] = xp[4]; xr[r][5] = xp[5];
            }
            #pragma unroll
            for (int k = 0; k < 9; k++) {
                const int ky = k / 3, kx = k % 3;
                const float* wp = &ws[(ci * 9 + k) * 80 + o0];
                #pragma unroll
                for (int o = 0; o < 5; o++) {
                    float wv = wp[o];
                    #pragma unroll
                    for (int r = 0; r < 2; r++)
                        #pragma unroll
                        for (int p = 0; p < 4; p++)
                            acc[o][r][p] = fmaf(wv, xr[r + ky][p + kx], acc[o][r][p]);
                }
            }
        }
    }

    #pragma unroll
    for (int o = 0; o < 5; o++) {
        int co = o0 + o;
        if (co < OFFC) {
            float bias = b_off[co];
            #pragma unroll
            for (int r = 0; r < 2; r++) {
                float4 v = make_float4(acc[o][r][0] + bias, acc[o][r][1] + bias,
                                       acc[o][r][2] + bias, acc[o][r][3] + bias);
                *(float4*)&g_off[((b * OFFC + co) * HH + h0 + r) * WW + w4] = v;
            }
        }
    }
}

// ---------------- stage 2: deformable conv via mma.sync tf32 ----------------
// Block (b, og, row-pair h0): D[64 co][128 px], 8 warps each own 16co x 64px.
// Per tap k: sample A'[cg][px] (tf32-rounded fp32) + stage W[cg][co], then
// warp MMA: A = W (m16 x k8, row-major over [co][cg]-transposed reads),
//           B = samples (k8 x n8, col-major = s[cg][px]).
__global__ void __launch_bounds__(256)
deform_conv_mma(const float* __restrict__ x, const float* __restrict__ b_def,
                float* __restrict__ out) {
    extern __shared__ float sm[];
    int*   pidx = (int*)sm;                  // [9*128][4]
    float* pwt  = sm + 9 * 128 * 4;          // [9*128][4]
    float* s    = sm + 2 * 9 * 128 * 4;      // [64][SPAD]
    float* wts  = s + CG * SPAD;             // [64][WPAD]

    const int b  = blockIdx.z;
    const int og = blockIdx.y;
    const int h0 = blockIdx.x * 2;
    const int t  = threadIdx.x;

    // ---- phase 1: bilinear params for 9 taps x 128 pixels ----
    const float* offp = g_off + (b * OFFC + og * 18) * (HH * WW);
    for (int e = t; e < 9 * 128; e += 256) {
        int k = e >> 7, p = e & 127;
        int r = p >> 6, w = p & 63;
        int h = h0 + r;
        float dy = offp[(2 * k) * (HH * WW) + h * WW + w];
        float dx = offp[(2 * k + 1) * (HH * WW) + h * WW + w];
        float py = dy + (float)(k / 3 - 1) + (float)h;
        float px = dx + (float)(k % 3 - 1) + (float)w;
        float fy = floorf(py), fx = floorf(px);
        int   y0 = (int)fy,   x0 = (int)fx;
        float ly = py - fy,   lx = px - fx;
        float wy0 = 1.f - ly, wx0 = 1.f - lx;
        float cw[4] = {wy0 * wx0, wy0 * lx, ly * wx0, ly * lx};
        int   ys[4] = {y0, y0, y0 + 1, y0 + 1};
        int   xc[4] = {x0, x0 + 1, x0, x0 + 1};
        int base = e * 4;
        #pragma unroll
        for (int j = 0; j < 4; j++) {
            bool v = (unsigned)ys[j] < (unsigned)HH && (unsigned)xc[j] < (unsigned)WW;
            pidx[base + j] = v ? ys[j] * WW + xc[j] : 0;
            pwt [base + j] = v ? cw[j] : 0.f;
        }
    }
    __syncthreads();

    const int lane = t & 31, wq = t >> 5;
    const int m0 = (wq & 3) * 16;     // co base for this warp
    const int n0 = (wq >> 2) * 64;    // px base for this warp
    const int lq = lane >> 2;         // groupID (0..7)
    const int lr = lane & 3;          // threadID in group (0..3)

    float acc[8][4];                  // 8 n-tiles x 4 accum regs
    #pragma unroll
    for (int nt = 0; nt < 8; nt++)
        #pragma unroll
        for (int j = 0; j < 4; j++) acc[nt][j] = 0.f;

    const float* xplane = x + (b * CIN + og * CG) * (HH * WW);
    const float* wsrc   = g_wdef_r + (og * 9) * (CG * CG);
    const int sp   = t & 127;           // sampling pixel (0..127)
    const int scg0 = (t >> 7) * 32;     // sampling channel base (0 or 32)

    #pragma unroll 1
    for (int k = 0; k < 9; k++) {
        // stage this tap's 64x64 weight slab (coalesced reads, padded rows)
        for (int j = t; j < CG * CG; j += 256) {
            int cg = j >> 6, co = j & 63;
            wts[cg * WPAD + co] = wsrc[k * CG * CG + j];
        }
        // sample 32 channels for my pixel, round to tf32
        const int4   iv = *(const int4*)  &pidx[(k * 128 + sp) * 4];
        const float4 wv = *(const float4*)&pwt [(k * 128 + sp) * 4];
        const float* xc = xplane + scg0 * (HH * WW);
        #pragma unroll 4
        for (int c = 0; c < 32; c++) {
            float v = wv.x * __ldg(xc + iv.x)
                    + wv.y * __ldg(xc + iv.y)
                    + wv.z * __ldg(xc + iv.z)
                    + wv.w * __ldg(xc + iv.w);
            s[(scg0 + c) * SPAD + sp] = to_tf32(v);
            xc += HH * WW;
        }
        __syncthreads();

        // A fragments (weights) for all 8 k-steps: A[m16][k8] where m=co, k=cg.
        // A row-major fragment: a0=(lq, lr) a1=(lq+8, lr) a2=(lq, lr+4) a3=(lq+8, lr+4)
        // wts is [cg][co] so element (m,kk) lives at wts[kk*WPAD + m] — read transposed:
        uint32_t af[8][4];
        #pragma unroll
        for (int ks = 0; ks < 8; ks++) {
            const int kk = ks * 8;
            af[ks][0] = __float_as_uint(wts[(kk + lr)     * WPAD + m0 + lq]);
            af[ks][1] = __float_as_uint(wts[(kk + lr)     * WPAD + m0 + lq + 8]);
            af[ks][2] = __float_as_uint(wts[(kk + lr + 4) * WPAD + m0 + lq]);
            af[ks][3] = __float_as_uint(wts[(kk + lr + 4) * WPAD + m0 + lq + 8]);
        }
        // hold on: A row-major (m,k): a0=(row m0+lq, col lr). wts[(cg)*WPAD+co] with
        // row=co=m0+lq, col=cg=lr  ->  wts[lr*WPAD + m0+lq]. a1: m+8; a2: k+4. Matches above.

        #pragma unroll
        for (int nt = 0; nt < 8; nt++) {
            const int n = n0 + nt * 8;
            #pragma unroll
            for (int ks = 0; ks < 8; ks++) {
                const int kk = ks * 8;
                // B col-major (k,n): b0=(kk+lr, n+lq), b1=(kk+lr+4, n+lq); s[cg][px]
                uint32_t b0 = __float_as_uint(s[(kk + lr)     * SPAD + n + lq]);
                uint32_t b1 = __float_as_uint(s[(kk + lr + 4) * SPAD + n + lq]);
                mma16n8k8(acc[nt], af[ks], b0, b1);
            }
        }
        __syncthreads();
    }

    // epilogue: d0,d1 -> (co=m0+lq, px=n+2*lr+{0,1}); d2,d3 -> co+8
    const float bias0 = b_def[og * CG + m0 + lq];
    const float bias1 = b_def[og * CG + m0 + lq + 8];
    #pragma unroll
    for (int nt = 0; nt < 8; nt++) {
        const int px = n0 + nt * 8 + 2 * lr;
        const int pr = px >> 6, pw = px & 63;
        float* op0 = out + ((size_t)(b * CIN + og * CG + m0 + lq) * HH + h0 + pr) * WW + pw;
        float2 v0 = make_float2(acc[nt][0] + bias0, acc[nt][1] + bias0);
        *(float2*)op0 = v0;
        float* op1 = op0 + 8 * (size_t)(HH * WW);
        float2 v1 = make_float2(acc[nt][2] + bias1, acc[nt][3] + bias1);
        *(float2*)op1 = v1;
    }
}

// ---------------- launch ----------------
extern "C" void kernel_launch(void* const* d_in, const int* in_sizes, int n_in,
                              void* d_out, int out_size) {
    const float* x     = (const float*)d_in[0];
    const float* w_off = (const float*)d_in[1];
    const float* b_off = (const float*)d_in[2];
    const float* w_def = (const float*)d_in[3];
    const float* b_def = (const float*)d_in[4];
    float* out = (float*)d_out;

    const int smem1 = (16 * 4 * 68 + 144 * 80) * 4;                       // 63488 B
    const int smem2 = (2 * 9 * 128 * 4 + CG * SPAD + CG * WPAD) * 4;      // 89088 B
    cudaFuncSetAttribute(offsets_conv,    cudaFuncAttributeMaxDynamicSharedMemorySize, smem1);
    cudaFuncSetAttribute(deform_conv_mma, cudaFuncAttributeMaxDynamicSharedMemorySize, smem2);

    reorder_weights<<<648, 256>>>(w_off, w_def);
    offsets_conv<<<dim3(HH / 2, BATCH), 256, smem1>>>(x, b_off);
    deform_conv_mma<<<dim3(HH / 2, OG, BATCH), 256, smem2>>>(x, b_def, out);
}

// round 12
// speedup vs baseline: 1.6093x; 1.5085x over previous
#include <cuda_runtime.h>
#include <cuda_bf16.h>
#include <cstdint>

// Problem constants: B=8, C=256, H=W=64, OG=4, Cg=64, K=9 taps, off channels=72.
#define BATCH 8
#define CIN   256
#define HH    64
#define WW    64
#define OG    4
#define CG    64
#define OFFC  72   // 2*9*OG

// stage-2 pads (proven conflict-free in R9)
#define SPAD 136
#define WPAD 68
// stage-1 pads: xs ci-row stride 66 floats; ws row stride 148 floats
#define XST  66
#define WST  148

// ---------------- device scratch (static, allocation-free) ----------------
__device__ float g_off[BATCH * OFFC * HH * WW];   // stage-1 output: offsets
__device__ float g_woff2[80 * 2304];              // w_off as [co(pad80)][chunk][tap][ci_l], tf32
__device__ float g_wdef_r[OG * 9 * CG * CG];      // w_def reordered [og][k][cg][co], tf32

__device__ __forceinline__ float to_tf32(float f) {
    uint32_t u;
    asm("cvt.rna.tf32.f32 %0, %1;" : "=r"(u) : "f"(f));
    return __uint_as_float(u);
}

// D(16x8) += A(16x8, row) * B(8x8, col), tf32 inputs, f32 accum
__device__ __forceinline__ void mma16n8k8(float* d, const uint32_t* a, uint32_t b0, uint32_t b1) {
    asm volatile(
        "mma.sync.aligned.m16n8k8.row.col.f32.tf32.tf32.f32 "
        "{%0,%1,%2,%3}, {%4,%5,%6,%7}, {%8,%9}, {%0,%1,%2,%3};"
        : "+f"(d[0]), "+f"(d[1]), "+f"(d[2]), "+f"(d[3])
        : "r"(a[0]), "r"(a[1]), "r"(a[2]), "r"(a[3]), "r"(b0), "r"(b1));
}

// ---------------- weight reorder (one-time-ish, tiny) ----------------
__global__ void reorder_weights(const float* __restrict__ w_off,
                                const float* __restrict__ w_def) {
    int i = blockIdx.x * 256 + threadIdx.x;
    // w_off [72][256][3][3] -> g_woff2[co][chunk][tap][ci_l] (co padded to 80 with zeros)
    if (i < 80 * 2304) {
        int co  = i / 2304, rem = i % 2304;
        int chunk = rem / 144, q = rem % 144;
        int tap = q / 16, ci_l = q % 16;
        float v = 0.f;
        if (co < OFFC)
            v = to_tf32(w_off[co * 2304 + (chunk * 16 + ci_l) * 9 + tap]);
        g_woff2[i] = v;
    }
    // w_def [256][64][3][3] -> g_wdef_r[((og*9+k)*64+cg)*64+co], tf32
    if (i < OG * 9 * CG * CG) {
        int co = i & 63;
        int t  = i >> 6;
        int cg = t & 63;
        t >>= 6;
        int k  = t % 9;
        int og = t / 9;
        g_wdef_r[i] = to_tf32(w_def[((og * CG + co) * CG + cg) * 9 + k]);
    }
}

// ---------------- stage 1: offsets conv via mma.sync tf32 ----------------
// Block (b, row-pair h0): D[80 co][128 px], 10 warps = 5 m-tiles x 2 n-tiles (16co x 64px).
// B fragments read straight from the x halo tile with per-tap shifted indices
// (implicit im2col). K = 16 chunks x 9 taps x 2 ksteps of 8 channels.
__global__ void __launch_bounds__(320)
offsets_conv_mma(const float* __restrict__ x, const float* __restrict__ b_off) {
    extern __shared__ float sm[];
    float* xs = sm;                 // [16 ci][4 rows][66 cols], ci-row stride 264
    float* ws = sm + 16 * 4 * XST;  // [80 co][148], cols 0..143 used

    const int b  = blockIdx.y;
    const int h0 = blockIdx.x * 2;
    const int t  = threadIdx.x;
    const int lane = t & 31, wq = t >> 5;
    const int m0 = (wq % 5) * 16;          // co base
    const int n0 = (wq / 5) * 64;          // px base
    const int lq = lane >> 2, lr = lane & 3;
    const int pr = n0 >> 6;                // output row within pair (0/1), const per warp

    float acc[8][4];
    #pragma unroll
    for (int nt = 0; nt < 8; nt++)
        #pragma unroll
        for (int j = 0; j < 4; j++) acc[nt][j] = 0.f;

    for (int chunk = 0; chunk < 16; chunk++) {
        const int ci0 = chunk * 16;
        __syncthreads();
        // stage x chunk: [16 ci][4 rows][66 cols], gw = c-1 in [-1, 64]
        for (int j = t; j < 16 * 4 * XST; j += 320) {
            int c  = j % XST;
            int rc = j / XST;
            int r  = rc & 3;
            int ci = rc >> 2;
            int gh = h0 - 1 + r, gw = c - 1;
            float v = 0.f;
            if ((unsigned)gh < (unsigned)HH && (unsigned)gw < (unsigned)WW)
                v = to_tf32(x[(((b << 8) + ci0 + ci) * HH + gh) * WW + gw]);
            xs[(ci * 4 + r) * XST + c] = v;
        }
        // stage weight chunk: [80 co][144] (float4 rows; WST%4==0 keeps alignment)
        for (int j4 = t; j4 < 80 * 36; j4 += 320) {
            int co = j4 / 36, c4 = j4 % 36;
            ((float4*)(ws + co * WST))[c4] =
                ((const float4*)(g_woff2 + co * 2304 + chunk * 144))[c4];
        }
        __syncthreads();

        #pragma unroll 1
        for (int tap = 0; tap < 9; tap++) {
            const int ky = tap / 3, kx = tap % 3;
            #pragma unroll
            for (int ks = 0; ks < 2; ks++) {
                const int kk = tap * 16 + ks * 8;
                // A frags: ws[co][kk+lr(+4)], rows m0+lq(+8)
                uint32_t af[4];
                af[0] = __float_as_uint(ws[(m0 + lq)     * WST + kk + lr]);
                af[1] = __float_as_uint(ws[(m0 + lq + 8) * WST + kk + lr]);
                af[2] = __float_as_uint(ws[(m0 + lq)     * WST + kk + lr + 4]);
                af[3] = __float_as_uint(ws[(m0 + lq + 8) * WST + kk + lr + 4]);
                const int cb0 = ((ks * 8 + lr)     * 4 + pr + ky) * XST + kx + lq;
                const int cb1 = ((ks * 8 + lr + 4) * 4 + pr + ky) * XST + kx + lq;
                #pragma unroll
                for (int nt = 0; nt < 8; nt++) {
                    // B col-major (k=ci, n=px): value = xs[ci][pr+ky][pw+kx], pw = nt*8+lq
                    uint32_t b0 = __float_as_uint(xs[cb0 + nt * 8]);
                    uint32_t b1 = __float_as_uint(xs[cb1 + nt * 8]);
                    mma16n8k8(acc[nt], af, b0, b1);
                }
            }
        }
    }

    // epilogue: rows co = m0+lq (+8), cols px = n0 + nt*8 + 2*lr (+1)
    const int co0 = m0 + lq, co1 = m0 + lq + 8;
    const float bias0 = (co0 < OFFC) ? b_off[co0] : 0.f;
    const float bias1 = (co1 < OFFC) ? b_off[co1] : 0.f;
    #pragma unroll
    for (int nt = 0; nt < 8; nt++) {
        const int pw = nt * 8 + 2 * lr;
        if (co0 < OFFC) {
            float* op = &g_off[((b * OFFC + co0) * HH + h0 + pr) * WW + pw];
            *(float2*)op = make_float2(acc[nt][0] + bias0, acc[nt][1] + bias0);
        }
        if (co1 < OFFC) {
            float* op = &g_off[((b * OFFC + co1) * HH + h0 + pr) * WW + pw];
            *(float2*)op = make_float2(acc[nt][2] + bias1, acc[nt][3] + bias1);
        }
    }
}

// ---------------- stage 2: deformable conv via mma.sync tf32 (unchanged from R9) ----------------
__global__ void __launch_bounds__(256)
deform_conv_mma(const float* __restrict__ x, const float* __restrict__ b_def,
                float* __restrict__ out) {
    extern __shared__ float sm[];
    int*   pidx = (int*)sm;                  // [9*128][4]
    float* pwt  = sm + 9 * 128 * 4;          // [9*128][4]
    float* s    = sm + 2 * 9 * 128 * 4;      // [64][SPAD]
    float* wts  = s + CG * SPAD;             // [64][WPAD]

    const int b  = blockIdx.z;
    const int og = blockIdx.y;
    const int h0 = blockIdx.x * 2;
    const int t  = threadIdx.x;

    const float* offp = g_off + (b * OFFC + og * 18) * (HH * WW);
    for (int e = t; e < 9 * 128; e += 256) {
        int k = e >> 7, p = e & 127;
        int r = p >> 6, w = p & 63;
        int h = h0 + r;
        float dy = offp[(2 * k) * (HH * WW) + h * WW + w];
        float dx = offp[(2 * k + 1) * (HH * WW) + h * WW + w];
        float py = dy + (float)(k / 3 - 1) + (float)h;
        float px = dx + (float)(k % 3 - 1) + (float)w;
        float fy = floorf(py), fx = floorf(px);
        int   y0 = (int)fy,   x0 = (int)fx;
        float ly = py - fy,   lx = px - fx;
        float wy0 = 1.f - ly, wx0 = 1.f - lx;
        float cw[4] = {wy0 * wx0, wy0 * lx, ly * wx0, ly * lx};
        int   ys[4] = {y0, y0, y0 + 1, y0 + 1};
        int   xc[4] = {x0, x0 + 1, x0, x0 + 1};
        int base = e * 4;
        #pragma unroll
        for (int j = 0; j < 4; j++) {
            bool v = (unsigned)ys[j] < (unsigned)HH && (unsigned)xc[j] < (unsigned)WW;
            pidx[base + j] = v ? ys[j] * WW + xc[j] : 0;
            pwt [base + j] = v ? cw[j] : 0.f;
        }
    }
    __syncthreads();

    const int lane = t & 31, wq = t >> 5;
    const int m0 = (wq & 3) * 16;
    const int n0 = (wq >> 2) * 64;
    const int lq = lane >> 2;
    const int lr = lane & 3;

    float acc[8][4];
    #pragma unroll
    for (int nt = 0; nt < 8; nt++)
        #pragma unroll
        for (int j = 0; j < 4; j++) acc[nt][j] = 0.f;

    const float* xplane = x + (b * CIN + og * CG) * (HH * WW);
    const float* wsrc   = g_wdef_r + (og * 9) * (CG * CG);
    const int sp   = t & 127;
    const int scg0 = (t >> 7) * 32;

    #pragma unroll 1
    for (int k = 0; k < 9; k++) {
        for (int j = t; j < CG * CG; j += 256) {
            int cg = j >> 6, co = j & 63;
            wts[cg * WPAD + co] = wsrc[k * CG * CG + j];
        }
        const int4   iv = *(const int4*)  &pidx[(k * 128 + sp) * 4];
        const float4 wv = *(const float4*)&pwt [(k * 128 + sp) * 4];
        const float* xc = xplane + scg0 * (HH * WW);
        #pragma unroll 4
        for (int c = 0; c < 32; c++) {
            float v = wv.x * __ldg(xc + iv.x)
                    + wv.y * __ldg(xc + iv.y)
                    + wv.z * __ldg(xc + iv.z)
                    + wv.w * __ldg(xc + iv.w);
            s[(scg0 + c) * SPAD + sp] = to_tf32(v);
            xc += HH * WW;
        }
        __syncthreads();

        uint32_t af[8][4];
        #pragma unroll
        for (int ks = 0; ks < 8; ks++) {
            const int kk = ks * 8;
            af[ks][0] = __float_as_uint(wts[(kk + lr)     * WPAD + m0 + lq]);
            af[ks][1] = __float_as_uint(wts[(kk + lr)     * WPAD + m0 + lq + 8]);
            af[ks][2] = __float_as_uint(wts[(kk + lr + 4) * WPAD + m0 + lq]);
            af[ks][3] = __float_as_uint(wts[(kk + lr + 4) * WPAD + m0 + lq + 8]);
        }

        #pragma unroll
        for (int nt = 0; nt < 8; nt++) {
            const int n = n0 + nt * 8;
            #pragma unroll
            for (int ks = 0; ks < 8; ks++) {
                const int kk = ks * 8;
                uint32_t b0 = __float_as_uint(s[(kk + lr)     * SPAD + n + lq]);
                uint32_t b1 = __float_as_uint(s[(kk + lr + 4) * SPAD + n + lq]);
                mma16n8k8(acc[nt], af[ks], b0, b1);
            }
        }
        __syncthreads();
    }

    const float bias0 = b_def[og * CG + m0 + lq];
    const float bias1 = b_def[og * CG + m0 + lq + 8];
    #pragma unroll
    for (int nt = 0; nt < 8; nt++) {
        const int px = n0 + nt * 8 + 2 * lr;
        const int pr = px >> 6, pw = px & 63;
        float* op0 = out + ((size_t)(b * CIN + og * CG + m0 + lq) * HH + h0 + pr) * WW + pw;
        *(float2*)op0 = make_float2(acc[nt][0] + bias0, acc[nt][1] + bias0);
        float* op1 = op0 + 8 * (size_t)(HH * WW);
        *(float2*)op1 = make_float2(acc[nt][2] + bias1, acc[nt][3] + bias1);
    }
}

// ---------------- launch ----------------
extern "C" void kernel_launch(void* const* d_in, const int* in_sizes, int n_in,
                              void* d_out, int out_size) {
    const float* x     = (const float*)d_in[0];
    const float* w_off = (const float*)d_in[1];
    const float* b_off = (const float*)d_in[2];
    const float* w_def = (const float*)d_in[3];
    const float* b_def = (const float*)d_in[4];
    float* out = (float*)d_out;

    const int smem1 = (16 * 4 * XST + 80 * WST) * 4;                  // 64256 B
    const int smem2 = (2 * 9 * 128 * 4 + CG * SPAD + CG * WPAD) * 4;  // 89088 B
    cudaFuncSetAttribute(offsets_conv_mma, cudaFuncAttributeMaxDynamicSharedMemorySize, smem1);
    cudaFuncSetAttribute(deform_conv_mma,  cudaFuncAttributeMaxDynamicSharedMemorySize, smem2);

    reorder_weights<<<720, 256>>>(w_off, w_def);
    offsets_conv_mma<<<dim3(HH / 2, BATCH), 320, smem1>>>(x, b_off);
    deform_conv_mma<<<dim3(HH / 2, OG, BATCH), 256, smem2>>>(x, b_def, out);
}

// round 14
// speedup vs baseline: 2.9851x; 1.8549x over previous
#include <cuda_runtime.h>
#include <cuda_bf16.h>
#include <cuda_fp16.h>
#include <cstdint>

// Problem constants: B=8, C=256, H=W=64, OG=4, Cg=64, K=9 taps, off channels=72.
#define BATCH 8
#define CIN   256
#define HH    64
#define WW    64
#define OG    4
#define CG    64
#define OFFC  72   // 2*9*OG
#define HW    (HH * WW)

// ---------------- device scratch (static, allocation-free) ----------------
__device__ float    g_off[BATCH * OFFC * HH * WW];   // stage-1 output: offsets (fp32)
__device__ uint32_t g_woff2[16 * 80 * 76];           // stage-1 W: [chunk][co pad80][tap*8+pair pad76] half2
__device__ uint32_t g_wdef2[OG * 9 * 64 * 32];       // stage-2 W: [og][tap][co][cg-pair] half2

__device__ __forceinline__ uint32_t pack_h2(float lo, float hi) {
    __half2 h = __floats2half2_rn(lo, hi);
    return *(uint32_t*)&h;
}

// D(16x8,f32) += A(16x16 f16, row) * B(16x8 f16, col)
__device__ __forceinline__ void mma16n8k16(float* d, const uint32_t* a, uint32_t b0, uint32_t b1) {
    asm volatile(
        "mma.sync.aligned.m16n8k16.row.col.f32.f16.f16.f32 "
        "{%0,%1,%2,%3}, {%4,%5,%6,%7}, {%8,%9}, {%0,%1,%2,%3};"
        : "+f"(d[0]), "+f"(d[1]), "+f"(d[2]), "+f"(d[3])
        : "r"(a[0]), "r"(a[1]), "r"(a[2]), "r"(a[3]), "r"(b0), "r"(b1));
}

// ---------------- weight reorder (one-time-ish, tiny) ----------------
__global__ void reorder_weights(const float* __restrict__ w_off,
                                const float* __restrict__ w_def) {
    int i = blockIdx.x * 256 + threadIdx.x;
    // w_off [72 co][256 ci][3][3] -> g_woff2[chunk][co][tap*8 + pair] = half2{ci=2pair, 2pair+1}
    if (i < 16 * 80 * 76) {
        int chunk = i / (80 * 76), rem = i % (80 * 76);
        int co = rem / 76, q = rem % 76;
        int tap = q >> 3, pr = q & 7;
        uint32_t v = 0;
        if (co < OFFC && tap < 9) {
            int ci = chunk * 16 + 2 * pr;
            v = pack_h2(w_off[co * 2304 + ci * 9 + tap],
                        w_off[co * 2304 + (ci + 1) * 9 + tap]);
        }
        g_woff2[i] = v;
    }
    // w_def [256][64][3][3] -> g_wdef2[og][tap][co][pair] = half2{cg=2pair, 2pair+1}
    if (i < OG * 9 * 64 * 32) {
        int p  = i & 31;
        int r  = i >> 5;
        int co = r & 63; r >>= 6;
        int tap = r % 9, og = r / 9;
        g_wdef2[i] = pack_h2(w_def[((og * CG + co) * CG + 2 * p) * 9 + tap],
                             w_def[((og * CG + co) * CG + 2 * p + 1) * 9 + tap]);
    }
}

// ---------------- stage 1: offsets conv via mma.sync fp16 (k16 = one ci-chunk) ----------------
// Block (b, row-pair h0): D[80 co][128 px], 10 warps = 5 m-tiles x 2 n-tiles (16co x 64px).
// Implicit im2col: B fragments read from x halo tile with per-tap shifted indices.
// xs layout: [4 rows][66 cols][12 ci-pairs pad] half2   (12*lq+lr banks distinct)
// ws layout: [80 co][76 = 9 taps * 8 pairs pad] half2   (12*lq+lr banks distinct)
__global__ void __launch_bounds__(320)
offsets_conv_mma(const float* __restrict__ x, const float* __restrict__ b_off) {
    extern __shared__ float sm[];
    uint32_t* x2 = (uint32_t*)sm;            // 4*66*12 = 3168 uints (12672 B)
    uint32_t* ws = x2 + 4 * 66 * 12;         // 80*76   = 6080 uints (24320 B)

    const int b  = blockIdx.y;
    const int h0 = blockIdx.x * 2;
    const int t  = threadIdx.x;
    const int lane = t & 31, wq = t >> 5;
    const int m0 = (wq % 5) * 16;          // co base
    const int n0 = (wq / 5) * 64;          // px base
    const int lq = lane >> 2, lr = lane & 3;
    const int pr = n0 >> 6;                // output row within pair (0/1), const per warp

    float acc[8][4];
    #pragma unroll
    for (int nt = 0; nt < 8; nt++)
        #pragma unroll
        for (int j = 0; j < 4; j++) acc[nt][j] = 0.f;

    for (int chunk = 0; chunk < 16; chunk++) {
        const int ci0 = chunk * 16;
        __syncthreads();
        // stage x chunk: 8 ci-pairs x 4 rows x 66 cols (halo), fp16-packed
        for (int j = t; j < 8 * 4 * 66; j += 320) {
            int p  = j / 264;
            int rc = j % 264;
            int r  = rc / 66, c = rc % 66;
            int gh = h0 - 1 + r, gw = c - 1;
            float v0 = 0.f, v1 = 0.f;
            if ((unsigned)gh < (unsigned)HH && (unsigned)gw < (unsigned)WW) {
                const float* xp = x + (((b << 8) + ci0 + 2 * p) * HH + gh) * WW + gw;
                v0 = xp[0];
                v1 = xp[HW];
            }
            x2[(r * 66 + c) * 12 + p] = pack_h2(v0, v1);
        }
        // stage weight chunk: straight flat copy (same layout in gmem)
        {
            const uint4* src = (const uint4*)(g_woff2 + chunk * 80 * 76);
            uint4* dst = (uint4*)ws;
            for (int j4 = t; j4 < 80 * 76 / 4; j4 += 320)
                dst[j4] = src[j4];
        }
        __syncthreads();

        #pragma unroll
        for (int tap = 0; tap < 9; tap++) {
            const int ky = tap / 3, kx = tap % 3;
            // A frags: k16 = this chunk's 16 ci, rows m0+lq(+8)
            uint32_t af[4];
            af[0] = ws[(m0 + lq)     * 76 + tap * 8 + lr];
            af[1] = ws[(m0 + lq + 8) * 76 + tap * 8 + lr];
            af[2] = ws[(m0 + lq)     * 76 + tap * 8 + 4 + lr];
            af[3] = ws[(m0 + lq + 8) * 76 + tap * 8 + 4 + lr];
            const int cb = ((pr + ky) * 66 + kx + lq) * 12;
            #pragma unroll
            for (int nt = 0; nt < 8; nt++) {
                // B col-major (k=ci, n=px): pixel = nt*8+lq, pairs lr and 4+lr
                uint32_t b0 = x2[cb + nt * 96 + lr];      // (nt*8)*12 = 96
                uint32_t b1 = x2[cb + nt * 96 + 4 + lr];
                mma16n8k16(acc[nt], af, b0, b1);
            }
        }
    }

    // epilogue: rows co = m0+lq (+8), cols px = n0 + nt*8 + 2*lr (+1)
    const int co0 = m0 + lq, co1 = m0 + lq + 8;
    const float bias0 = (co0 < OFFC) ? b_off[co0] : 0.f;
    const float bias1 = (co1 < OFFC) ? b_off[co1] : 0.f;
    #pragma unroll
    for (int nt = 0; nt < 8; nt++) {
        const int pw = nt * 8 + 2 * lr;
        if (co0 < OFFC) {
            float* op = &g_off[((b * OFFC + co0) * HH + h0 + pr) * WW + pw];
            *(float2*)op = make_float2(acc[nt][0] + bias0, acc[nt][1] + bias0);
        }
        if (co1 < OFFC) {
            float* op = &g_off[((b * OFFC + co1) * HH + h0 + pr) * WW + pw];
            *(float2*)op = make_float2(acc[nt][2] + bias1, acc[nt][3] + bias1);
        }
    }
}

// ---------------- stage 2: deformable conv via mma.sync fp16 ----------------
// Block (b, og, row-pair h0): D[64 co][128 px], 8 warps each own 16co x 64px.
// s2 layout: [32 cg-pairs][136 px pad] half2  (reads 8lr+lq distinct; writes consecutive)
// wt2 layout: [64 co][36 cg-pairs pad] half2  (reads 4lq+lr distinct)
__global__ void __launch_bounds__(256)
deform_conv_mma(const float* __restrict__ x, const float* __restrict__ b_def,
                float* __restrict__ out) {
    extern __shared__ float sm[];
    int*      pidx = (int*)sm;                    // [9*128][4]  (18432 B)
    float*    pwt  = sm + 9 * 128 * 4;            // [9*128][4]  (18432 B)
    uint32_t* s2   = (uint32_t*)(sm + 2 * 9 * 128 * 4);  // 32*136 uints (17408 B)
    uint32_t* wt2  = s2 + 32 * 136;               // 64*36 uints (9216 B)

    const int b  = blockIdx.z;
    const int og = blockIdx.y;
    const int h0 = blockIdx.x * 2;
    const int t  = threadIdx.x;

    // ---- phase 1: bilinear params for 9 taps x 128 pixels ----
    const float* offp = g_off + (b * OFFC + og * 18) * HW;
    for (int e = t; e < 9 * 128; e += 256) {
        int k = e >> 7, p = e & 127;
        int r = p >> 6, w = p & 63;
        int h = h0 + r;
        float dy = offp[(2 * k) * HW + h * WW + w];
        float dx = offp[(2 * k + 1) * HW + h * WW + w];
        float py = dy + (float)(k / 3 - 1) + (float)h;
        float px = dx + (float)(k % 3 - 1) + (float)w;
        float fy = floorf(py), fx = floorf(px);
        int   y0 = (int)fy,   x0 = (int)fx;
        float ly = py - fy,   lx = px - fx;
        float wy0 = 1.f - ly, wx0 = 1.f - lx;
        float cw[4] = {wy0 * wx0, wy0 * lx, ly * wx0, ly * lx};
        int   ys[4] = {y0, y0, y0 + 1, y0 + 1};
        int   xc[4] = {x0, x0 + 1, x0, x0 + 1};
        int base = e * 4;
        #pragma unroll
        for (int j = 0; j < 4; j++) {
            bool v = (unsigned)ys[j] < (unsigned)HH && (unsigned)xc[j] < (unsigned)WW;
            pidx[base + j] = v ? ys[j] * WW + xc[j] : 0;
            pwt [base + j] = v ? cw[j] : 0.f;
        }
    }
    __syncthreads();

    const int lane = t & 31, wq = t >> 5;
    const int m0 = (wq & 3) * 16;
    const int n0 = (wq >> 2) * 64;
    const int lq = lane >> 2;
    const int lr = lane & 3;

    float acc[8][4];
    #pragma unroll
    for (int nt = 0; nt < 8; nt++)
        #pragma unroll
        for (int j = 0; j < 4; j++) acc[nt][j] = 0.f;

    const float* xplane = x + (b * CIN + og * CG) * HW;
    const uint32_t* wsrc = g_wdef2 + (og * 9) * (64 * 32);
    const int sp    = t & 127;          // sampling pixel
    const int spr0  = (t >> 7) * 16;    // sampling cg-pair base (0 or 16)

    #pragma unroll 1
    for (int k = 0; k < 9; k++) {
        // stage this tap's weight slab: [64 co][32 pairs] -> stride-36 rows
        {
            const uint32_t* srcw = wsrc + k * (64 * 32);
            for (int j = t; j < 64 * 32; j += 256) {
                int co = j >> 5, p = j & 31;
                wt2[co * 36 + p] = srcw[j];
            }
        }
        // sample 16 cg-pairs (32 channels) for my pixel, pack to half2
        const int4   iv = *(const int4*)  &pidx[(k * 128 + sp) * 4];
        const float4 wv = *(const float4*)&pwt [(k * 128 + sp) * 4];
        const float* xc = xplane + 2 * spr0 * HW;
        #pragma unroll 4
        for (int c2 = 0; c2 < 16; c2++) {
            float v0 = wv.x * __ldg(xc + iv.x) + wv.y * __ldg(xc + iv.y)
                     + wv.z * __ldg(xc + iv.z) + wv.w * __ldg(xc + iv.w);
            xc += HW;
            float v1 = wv.x * __ldg(xc + iv.x) + wv.y * __ldg(xc + iv.y)
                     + wv.z * __ldg(xc + iv.z) + wv.w * __ldg(xc + iv.w);
            xc += HW;
            s2[(spr0 + c2) * 136 + sp] = pack_h2(v0, v1);
        }
        __syncthreads();

        // A fragments: 4 k-steps of k16 (= 8 cg-pairs each)
        uint32_t af[4][4];
        #pragma unroll
        for (int ks = 0; ks < 4; ks++) {
            af[ks][0] = wt2[(m0 + lq)     * 36 + ks * 8 + lr];
            af[ks][1] = wt2[(m0 + lq + 8) * 36 + ks * 8 + lr];
            af[ks][2] = wt2[(m0 + lq)     * 36 + ks * 8 + 4 + lr];
            af[ks][3] = wt2[(m0 + lq + 8) * 36 + ks * 8 + 4 + lr];
        }

        #pragma unroll
        for (int nt = 0; nt < 8; nt++) {
            const int n = n0 + nt * 8;
            #pragma unroll
            for (int ks = 0; ks < 4; ks++) {
                uint32_t b0 = s2[(ks * 8 + lr)     * 136 + n + lq];
                uint32_t b1 = s2[(ks * 8 + 4 + lr) * 136 + n + lq];
                mma16n8k16(acc[nt], af[ks], b0, b1);
            }
        }
        __syncthreads();
    }

    const float bias0 = b_def[og * CG + m0 + lq];
    const float bias1 = b_def[og * CG + m0 + lq + 8];
    #pragma unroll
    for (int nt = 0; nt < 8; nt++) {
        const int px = n0 + nt * 8 + 2 * lr;
        const int prr = px >> 6, pw = px & 63;
        float* op0 = out + ((size_t)(b * CIN + og * CG + m0 + lq) * HH + h0 + prr) * WW + pw;
        *(float2*)op0 = make_float2(acc[nt][0] + bias0, acc[nt][1] + bias0);
        float* op1 = op0 + 8 * (size_t)HW;
        *(float2*)op1 = make_float2(acc[nt][2] + bias1, acc[nt][3] + bias1);
    }
}

// ---------------- launch ----------------
extern "C" void kernel_launch(void* const* d_in, const int* in_sizes, int n_in,
                              void* d_out, int out_size) {
    const float* x     = (const float*)d_in[0];
    const float* w_off = (const float*)d_in[1];
    const float* b_off = (const float*)d_in[2];
    const float* w_def = (const float*)d_in[3];
    const float* b_def = (const float*)d_in[4];
    float* out = (float*)d_out;

    const int smem1 = (4 * 66 * 12 + 80 * 76) * 4;                    // 36992 B
    const int smem2 = (2 * 9 * 128 * 4) * 4 + (32 * 136 + 64 * 36) * 4;  // 63488 B
    cudaFuncSetAttribute(offsets_conv_mma, cudaFuncAttributeMaxDynamicSharedMemorySize, smem1);
    cudaFuncSetAttribute(deform_conv_mma,  cudaFuncAttributeMaxDynamicSharedMemorySize, smem2);

    reorder_weights<<<380, 256>>>(w_off, w_def);
    offsets_conv_mma<<<dim3(HH / 2, BATCH), 320, smem1>>>(x, b_off);
    deform_conv_mma<<<dim3(HH / 2, OG, BATCH), 256, smem2>>>(x, b_def, out);
}